// round 3
// baseline (speedup 1.0000x reference)
#include <cuda_runtime.h>
#include <math.h>

// Problem constants
#define NB 128      // batch
#define NP 196      // pixels
#define ND 512      // ENC = H = E = A = 512
#define NV 32000    // vocab
#define NL 20       // caption length
#define NT 19       // decode steps
#define ZK 1536     // concat K for gates GEMM  [emb(512) awe(512) h(512)]
#define NG 2048     // 4*H

// ---------------------------------------------------------------------------
// Scratch (device globals; no allocations allowed)
// ---------------------------------------------------------------------------
__device__ float g_att1[(size_t)NB * NP * ND];   // 51.4 MB
__device__ float g_fmean[NB * ND];
__device__ float g_h[NB * ND];
__device__ float g_c[NB * ND];
__device__ float g_hnew[NB * ND];
__device__ float g_att2[NB * ND];
__device__ float g_gatepre[NB * ND];
__device__ float g_e[NB * NP];
__device__ float g_alpha[NB * NP];
__device__ float g_z[NB * ZK];
__device__ float g_gates[NB * NG];
__device__ float g_wcat[(size_t)NG * ZK];        // 12.6 MB packed [w_ih | w_hh]
__device__ float g_bcat[NG];

__device__ __forceinline__ float sigf(float x) { return 1.0f / (1.0f + expf(-x)); }

// ---------------------------------------------------------------------------
// Generic tiled SGEMM:  C[m,n] = sum_k A[m,K]*W[n,K] + bias[n]
// A: MxK row-major, W: NxK row-major (i.e. computes A @ W^T).
// Requires M%64==0, N%64==0, K%16==0 (true for all call sites).
// Optional mask: if lengths != nullptr, rows with (t >= lengths[m]-1) write 0.
// Output at C[coff + m*ldc + n].
// ---------------------------------------------------------------------------
#define BM 64
#define BN 64
#define BK 16

__global__ __launch_bounds__(256) void sgemm_nt(
    const float* __restrict__ A, const float* __restrict__ W,
    const float* __restrict__ bias, float* __restrict__ C,
    int M, int N, int K, long ldc, long coff,
    const int* __restrict__ lengths, int t)
{
    __shared__ float As[BK][BM];
    __shared__ float Ws[BK][BN];

    const int bm = blockIdx.y * BM;
    const int bn = blockIdx.x * BN;
    const int tid = threadIdx.x;
    const int tr  = tid >> 4;    // 0..15  (row group)
    const int tc  = tid & 15;    // 0..15  (col group)
    const int lr  = tid >> 2;    // 0..63  (load row)
    const int lk  = (tid & 3) * 4;

    float acc[4][4];
#pragma unroll
    for (int i = 0; i < 4; i++)
#pragma unroll
        for (int j = 0; j < 4; j++) acc[i][j] = 0.f;

    for (int k0 = 0; k0 < K; k0 += BK) {
        float4 av = *(const float4*)(&A[(long)(bm + lr) * K + k0 + lk]);
        As[lk + 0][lr] = av.x; As[lk + 1][lr] = av.y;
        As[lk + 2][lr] = av.z; As[lk + 3][lr] = av.w;
        float4 wv = *(const float4*)(&W[(long)(bn + lr) * K + k0 + lk]);
        Ws[lk + 0][lr] = wv.x; Ws[lk + 1][lr] = wv.y;
        Ws[lk + 2][lr] = wv.z; Ws[lk + 3][lr] = wv.w;
        __syncthreads();

#pragma unroll
        for (int kk = 0; kk < BK; kk++) {
            float4 a4 = *(const float4*)(&As[kk][tr * 4]);
            float4 w4 = *(const float4*)(&Ws[kk][tc * 4]);
            float a[4] = {a4.x, a4.y, a4.z, a4.w};
            float w[4] = {w4.x, w4.y, w4.z, w4.w};
#pragma unroll
            for (int i = 0; i < 4; i++)
#pragma unroll
                for (int j = 0; j < 4; j++) acc[i][j] = fmaf(a[i], w[j], acc[i][j]);
        }
        __syncthreads();
    }

#pragma unroll
    for (int i = 0; i < 4; i++) {
        int row = bm + tr * 4 + i;
        int act = 1;
        if (lengths) act = (t < lengths[row] - 1) ? 1 : 0;
#pragma unroll
        for (int j = 0; j < 4; j++) {
            int col = bn + tc * 4 + j;
            float v = acc[i][j] + (bias ? bias[col] : 0.f);
            if (!act) v = 0.f;
            C[coff + (long)row * ldc + col] = v;
        }
    }
}

// ---------------------------------------------------------------------------
// Small kernels
// ---------------------------------------------------------------------------
__global__ void k_fmean(const float* __restrict__ features)
{
    int b = blockIdx.x, e = threadIdx.x;              // 512 threads
    const float* f = features + (long)b * NP * ND + e;
    float s = 0.f;
#pragma unroll 4
    for (int p = 0; p < NP; p++) s += f[(long)p * ND];
    g_fmean[b * ND + e] = s * (1.0f / (float)NP);
}

__global__ void k_pack(const float* __restrict__ w_ih, const float* __restrict__ w_hh,
                       const float* __restrict__ b_ih, const float* __restrict__ b_hh)
{
    long idx = (long)blockIdx.x * blockDim.x + threadIdx.x;
    const long total = (long)NG * ZK;
    if (idx < total) {
        int j = (int)(idx / ZK);
        int k = (int)(idx % ZK);
        g_wcat[idx] = (k < 1024) ? w_ih[(long)j * 1024 + k]
                                 : w_hh[(long)j * 512 + (k - 1024)];
    }
    if (idx < NG) g_bcat[idx] = b_ih[idx] + b_hh[idx];
}

// e[b,p] = sum_a relu(att1[b,p,a] + att2[b,a]) * w_full[a]
__global__ void k_escore(const float* __restrict__ w_full)
{
    int warp = (int)((blockIdx.x * blockDim.x + threadIdx.x) >> 5);
    int lane = threadIdx.x & 31;
    if (warp >= NB * NP) return;
    int b = warp / NP;
    const float* a1 = g_att1 + (long)warp * ND;
    const float* a2 = g_att2 + b * ND;
    float s = 0.f;
    for (int k = lane; k < ND; k += 32) {
        float v = a1[k] + a2[k];
        s = fmaf(fmaxf(v, 0.f), w_full[k], s);
    }
#pragma unroll
    for (int o = 16; o > 0; o >>= 1) s += __shfl_xor_sync(0xffffffffu, s, o);
    if (lane == 0) g_e[warp] = s;
}

// softmax over P per batch; write alpha + masked alpha output
__global__ void k_softmax(const int* __restrict__ lengths, float* __restrict__ out,
                          long alpha_off, int t)
{
    int b = blockIdx.x;
    int p = threadIdx.x;  // 256 threads
    __shared__ float red[256];
    float orig = (p < NP) ? g_e[b * NP + p] : -1e30f;
    red[p] = orig; __syncthreads();
#pragma unroll
    for (int s = 128; s > 0; s >>= 1) { if (p < s) red[p] = fmaxf(red[p], red[p + s]); __syncthreads(); }
    float mx = red[0];
    __syncthreads();
    float ex = (p < NP) ? expf(orig - mx) : 0.f;
    red[p] = ex; __syncthreads();
#pragma unroll
    for (int s = 128; s > 0; s >>= 1) { if (p < s) red[p] += red[p + s]; __syncthreads(); }
    float inv = 1.0f / red[0];
    if (p < NP) {
        float a = ex * inv;
        g_alpha[b * NP + p] = a;
        int act = (t < lengths[b] - 1) ? 1 : 0;
        out[alpha_off + ((long)b * NT + t) * NP + p] = act ? a : 0.f;
    }
}

// z[b, 0:512]    = embed_w[captions[b,t]]
// z[b, 1024:1536]= h (pre-update)
__global__ void k_fillz(const float* __restrict__ embed_w,
                        const int* __restrict__ captions, int t)
{
    int b = blockIdx.x, e = threadIdx.x;
    int tok = captions[b * NL + t];
    g_z[b * ZK + e] = embed_w[(long)tok * ND + e];
    g_z[b * ZK + 1024 + e] = g_h[b * ND + e];
}

// z[b, 512:1024] = sigmoid(gatepre) * (alpha @ features)
__global__ void k_awe(const float* __restrict__ features)
{
    int b = blockIdx.x, e = threadIdx.x;              // 512 threads
    __shared__ float al[NP];
    for (int p = threadIdx.x; p < NP; p += blockDim.x) al[p] = g_alpha[b * NP + p];
    __syncthreads();
    const float* f = features + (long)b * NP * ND + e;
    float s = 0.f;
#pragma unroll 4
    for (int p = 0; p < NP; p++) s = fmaf(al[p], f[(long)p * ND], s);
    float gate = sigf(g_gatepre[b * ND + e]);
    g_z[b * ZK + 512 + e] = s * gate;
}

__global__ void k_lstm(const int* __restrict__ lengths, int t)
{
    int b = blockIdx.x, j = threadIdx.x;              // 512 threads
    const float* g = g_gates + b * NG;
    float ig = sigf(g[j]);
    float fg = sigf(g[512 + j]);
    float gg = tanhf(g[1024 + j]);
    float og = sigf(g[1536 + j]);
    float cold = g_c[b * ND + j], hold = g_h[b * ND + j];
    float cn = fg * cold + ig * gg;
    float hn = og * tanhf(cn);
    g_hnew[b * ND + j] = hn;
    int act = (t < lengths[b] - 1) ? 1 : 0;
    g_h[b * ND + j] = act ? hn : hold;
    g_c[b * ND + j] = act ? cn : cold;
}

// ---------------------------------------------------------------------------
// Launch
// ---------------------------------------------------------------------------
static inline void sgemm(const float* A, const float* W, const float* bias,
                         float* C, int M, int N, int K, long ldc, long coff,
                         const int* lengths, int t)
{
    dim3 grid(N / BN, M / BM);
    sgemm_nt<<<grid, 256>>>(A, W, bias, C, M, N, K, ldc, coff, lengths, t);
}

extern "C" void kernel_launch(void* const* d_in, const int* in_sizes, int n_in,
                              void* d_out, int out_size)
{
    const float* features = (const float*)d_in[0];
    const int*   captions = (const int*)  d_in[1];
    const int*   lengths  = (const int*)  d_in[2];
    const float* w_enc_att= (const float*)d_in[3];
    const float* b_enc_att= (const float*)d_in[4];
    const float* w_dec_att= (const float*)d_in[5];
    const float* b_dec_att= (const float*)d_in[6];
    const float* w_full   = (const float*)d_in[7];
    // d_in[8] = b_full : constant shift, softmax-invariant, e not emitted -> unused
    const float* embed_w  = (const float*)d_in[9];
    const float* w_ih     = (const float*)d_in[10];
    const float* b_ih     = (const float*)d_in[11];
    const float* w_hh     = (const float*)d_in[12];
    const float* b_hh     = (const float*)d_in[13];
    const float* w_init_h = (const float*)d_in[14];
    const float* b_init_h = (const float*)d_in[15];
    const float* w_init_c = (const float*)d_in[16];
    const float* b_init_c = (const float*)d_in[17];
    const float* w_beta   = (const float*)d_in[18];
    const float* b_beta   = (const float*)d_in[19];
    const float* w_fc     = (const float*)d_in[20];
    const float* b_fc     = (const float*)d_in[21];
    float* out = (float*)d_out;

    // Resolve device-global scratch addresses
    float *p_att1, *p_fmean, *p_h, *p_c, *p_hnew, *p_att2, *p_gatepre,
          *p_z, *p_gates, *p_wcat, *p_bcat;
    cudaGetSymbolAddress((void**)&p_att1,    g_att1);
    cudaGetSymbolAddress((void**)&p_fmean,   g_fmean);
    cudaGetSymbolAddress((void**)&p_h,       g_h);
    cudaGetSymbolAddress((void**)&p_c,       g_c);
    cudaGetSymbolAddress((void**)&p_hnew,    g_hnew);
    cudaGetSymbolAddress((void**)&p_att2,    g_att2);
    cudaGetSymbolAddress((void**)&p_gatepre, g_gatepre);
    cudaGetSymbolAddress((void**)&p_z,       g_z);
    cudaGetSymbolAddress((void**)&p_gates,   g_gates);
    cudaGetSymbolAddress((void**)&p_wcat,    g_wcat);
    cudaGetSymbolAddress((void**)&p_bcat,    g_bcat);

    const long PRED_SIZE = (long)NB * NT * NV;   // predictions block
    const long ALPHA_OFF = PRED_SIZE;            // alphas follow

    // ---- One-time setup (per replay; deterministic) ----
    k_fmean<<<NB, ND>>>(features);
    sgemm(p_fmean, w_init_h, b_init_h, p_h, NB, ND, ND, ND, 0, nullptr, 0);
    sgemm(p_fmean, w_init_c, b_init_c, p_c, NB, ND, ND, ND, 0, nullptr, 0);
    // att1 = features @ w_enc_att^T + b_enc_att  (25088 x 512, K=512)
    sgemm(features, w_enc_att, b_enc_att, p_att1, NB * NP, ND, ND, ND, 0, nullptr, 0);
    {
        long total = (long)NG * ZK;
        int blocks = (int)((total + 255) / 256);
        k_pack<<<blocks, 256>>>(w_ih, w_hh, b_ih, b_hh);
    }

    // ---- Decode loop ----
    for (int t = 0; t < NT; t++) {
        // att2 = h @ w_dec_att^T + b ; gatepre = h @ w_beta^T + b
        sgemm(p_h, w_dec_att, b_dec_att, p_att2,    NB, ND, ND, ND, 0, nullptr, 0);
        sgemm(p_h, w_beta,    b_beta,    p_gatepre, NB, ND, ND, ND, 0, nullptr, 0);

        // attention scores + softmax + context
        {
            int warps = NB * NP;
            int blocks = (warps * 32 + 255) / 256;
            k_escore<<<blocks, 256>>>(w_full);
        }
        k_softmax<<<NB, 256>>>(lengths, out, ALPHA_OFF, t);
        k_fillz<<<NB, ND>>>(embed_w, captions, t);
        k_awe<<<NB, ND>>>(features);

        // gates = z @ wcat^T + bcat   (128 x 2048, K=1536)
        sgemm(p_z, p_wcat, p_bcat, p_gates, NB, NG, ZK, NG, 0, nullptr, 0);

        k_lstm<<<NB, ND>>>(lengths, t);

        // preds = h_new @ w_fc^T + b_fc  (masked), written directly to output
        sgemm(p_hnew, w_fc, b_fc, out, NB, NV, ND,
              (long)NT * NV, (long)t * NV, lengths, t);
    }
}

// round 4
// speedup vs baseline: 1.6030x; 1.6030x over previous
#include <cuda_runtime.h>
#include <cuda_bf16.h>
#include <math.h>

// Problem constants
#define NB 128      // batch
#define NP 196      // pixels
#define ND 512      // ENC = H = E = A = 512
#define NV 32000    // vocab
#define NL 20       // caption length
#define NT 19       // decode steps
#define ZK 1536     // concat K for gates GEMM  [emb(512) awe(512) h(512)]
#define NG 2048     // 4*H
#define NAG 1024    // fused att2+beta output width

// ---------------------------------------------------------------------------
// Scratch (device globals; no allocations allowed)
// ---------------------------------------------------------------------------
__device__ float g_att1[(size_t)NB * NP * ND];              // 51.4 MB fp32
__device__ __nv_bfloat16 g_fhi[(size_t)NB * NP * ND];       // features hi
__device__ __nv_bfloat16 g_flo[(size_t)NB * NP * ND];       // features lo
__device__ __nv_bfloat16 g_wfch[(size_t)NV * ND];           // w_fc hi
__device__ __nv_bfloat16 g_wfcl[(size_t)NV * ND];           // w_fc lo
__device__ __nv_bfloat16 g_wcath[(size_t)NG * ZK];          // packed [w_ih|w_hh] hi
__device__ __nv_bfloat16 g_wcatl[(size_t)NG * ZK];
__device__ __nv_bfloat16 g_wench[(size_t)ND * ND];          // w_enc_att hi
__device__ __nv_bfloat16 g_wencl[(size_t)ND * ND];
__device__ float g_wag[(size_t)NAG * ND];                   // packed [w_dec_att|w_beta]
__device__ float g_bag[NAG];
__device__ float g_bcat[NG];
__device__ float g_fmean[NB * ND];
__device__ float g_h[NB * ND];
__device__ float g_c[NB * ND];
__device__ float g_att2gate[NB * NAG];                      // [att2 | gatepre]
__device__ float g_e[NB * NP];
__device__ float g_alpha[NB * NP];
__device__ float g_gates[NB * NG];
__device__ __nv_bfloat16 g_zhi[NB * ZK];
__device__ __nv_bfloat16 g_zlo[NB * ZK];
__device__ __nv_bfloat16 g_hnhi[NB * ND];
__device__ __nv_bfloat16 g_hnlo[NB * ND];

__device__ __forceinline__ float sigf(float x) { return 1.0f / (1.0f + expf(-x)); }

__device__ __forceinline__ void split2(float x, __nv_bfloat16* hi, __nv_bfloat16* lo)
{
    __nv_bfloat16 h = __float2bfloat16(x);
    *hi = h;
    *lo = __float2bfloat16(x - __bfloat162float(h));
}

// ---------------------------------------------------------------------------
// bf16x3 tensor-core GEMM:  C[m,n] = sum_k A[m,k]*W[n,k] + bias[n]
// A given as hi/lo bf16 (M x K row-major), W as hi/lo bf16 (N x K row-major).
// acc = Ah*Wh + Ah*Wl + Al*Wh  (fp32 accumulate)  ~ fp32 accuracy.
// BM=128, BN=64, BK=32, 256 threads = 8 warps (4 M-warps x 2 N-warps),
// warp tile 32x32 => 2x4 mma tiles of m16n8k16.
// Requires M%128==0, N%64==0, K%32==0. Optional row mask via lengths/t.
// ---------------------------------------------------------------------------
#define TBM 128
#define TBN 64
#define TBK 32
#define TLD 40   // BK + 8 pad (bf16 elems); row stride 80B -> conflict-free frags

__device__ __forceinline__ void mma16816(float* c, const unsigned* a, const unsigned* b)
{
    asm volatile(
        "mma.sync.aligned.m16n8k16.row.col.f32.bf16.bf16.f32 "
        "{%0,%1,%2,%3}, {%4,%5,%6,%7}, {%8,%9}, {%0,%1,%2,%3};\n"
        : "+f"(c[0]), "+f"(c[1]), "+f"(c[2]), "+f"(c[3])
        : "r"(a[0]), "r"(a[1]), "r"(a[2]), "r"(a[3]), "r"(b[0]), "r"(b[1]));
}

__global__ __launch_bounds__(256) void gemm_bf16x3(
    const __nv_bfloat16* __restrict__ Ah, const __nv_bfloat16* __restrict__ Al,
    const __nv_bfloat16* __restrict__ Wh, const __nv_bfloat16* __restrict__ Wl,
    const float* __restrict__ bias, float* __restrict__ C,
    int K, long ldc, long coff,
    const int* __restrict__ lengths, int t)
{
    __shared__ __nv_bfloat16 sAh[TBM * TLD];
    __shared__ __nv_bfloat16 sAl[TBM * TLD];
    __shared__ __nv_bfloat16 sWh[TBN * TLD];
    __shared__ __nv_bfloat16 sWl[TBN * TLD];

    const int tid  = threadIdx.x;
    const int wid  = tid >> 5;
    const int lane = tid & 31;
    const int g    = lane >> 2;
    const int tq   = lane & 3;
    const int mw   = (wid & 3) * 32;   // warp M base in tile
    const int nw   = (wid >> 2) * 32;  // warp N base in tile
    const long bm  = (long)blockIdx.y * TBM;
    const long bn  = (long)blockIdx.x * TBN;

    float acc[2][4][4];
#pragma unroll
    for (int mi = 0; mi < 2; mi++)
#pragma unroll
        for (int ni = 0; ni < 4; ni++)
#pragma unroll
            for (int q = 0; q < 4; q++) acc[mi][ni][q] = 0.f;

    for (int k0 = 0; k0 < K; k0 += TBK) {
        // ---- global -> smem (uint4 = 8 bf16) ----
#pragma unroll
        for (int i = 0; i < 2; i++) {
            int idx = tid + i * 256;
            int row = idx >> 2, c8 = (idx & 3) * 8;
            long goff = (bm + row) * (long)K + k0 + c8;
            *(uint4*)&sAh[row * TLD + c8] = *(const uint4*)&Ah[goff];
            *(uint4*)&sAl[row * TLD + c8] = *(const uint4*)&Al[goff];
        }
        {
            int row = tid >> 2, c8 = (tid & 3) * 8;
            long goff = (bn + row) * (long)K + k0 + c8;
            *(uint4*)&sWh[row * TLD + c8] = *(const uint4*)&Wh[goff];
            *(uint4*)&sWl[row * TLD + c8] = *(const uint4*)&Wl[goff];
        }
        __syncthreads();

        // ---- compute: 2 k-steps of 16 ----
#pragma unroll
        for (int ks = 0; ks < TBK; ks += 16) {
            unsigned ah[2][4], al[2][4], bh[4][2], bl[4][2];
            const int kc = ks + tq * 2;
#pragma unroll
            for (int mi = 0; mi < 2; mi++) {
                int r0 = mw + mi * 16 + g;
                ah[mi][0] = *(const unsigned*)&sAh[r0 * TLD + kc];
                ah[mi][1] = *(const unsigned*)&sAh[(r0 + 8) * TLD + kc];
                ah[mi][2] = *(const unsigned*)&sAh[r0 * TLD + kc + 8];
                ah[mi][3] = *(const unsigned*)&sAh[(r0 + 8) * TLD + kc + 8];
                al[mi][0] = *(const unsigned*)&sAl[r0 * TLD + kc];
                al[mi][1] = *(const unsigned*)&sAl[(r0 + 8) * TLD + kc];
                al[mi][2] = *(const unsigned*)&sAl[r0 * TLD + kc + 8];
                al[mi][3] = *(const unsigned*)&sAl[(r0 + 8) * TLD + kc + 8];
            }
#pragma unroll
            for (int ni = 0; ni < 4; ni++) {
                int wr = nw + ni * 8 + g;
                bh[ni][0] = *(const unsigned*)&sWh[wr * TLD + kc];
                bh[ni][1] = *(const unsigned*)&sWh[wr * TLD + kc + 8];
                bl[ni][0] = *(const unsigned*)&sWl[wr * TLD + kc];
                bl[ni][1] = *(const unsigned*)&sWl[wr * TLD + kc + 8];
            }
#pragma unroll
            for (int mi = 0; mi < 2; mi++)
#pragma unroll
                for (int ni = 0; ni < 4; ni++) {
                    mma16816(acc[mi][ni], ah[mi], bh[ni]);
                    mma16816(acc[mi][ni], ah[mi], bl[ni]);
                    mma16816(acc[mi][ni], al[mi], bh[ni]);
                }
        }
        __syncthreads();
    }

    // ---- epilogue ----
#pragma unroll
    for (int mi = 0; mi < 2; mi++) {
        int r0 = mw + mi * 16 + g;
        long row0 = bm + r0, row1 = row0 + 8;
        int act0 = 1, act1 = 1;
        if (lengths) {
            act0 = (t < lengths[row0] - 1) ? 1 : 0;
            act1 = (t < lengths[row1] - 1) ? 1 : 0;
        }
#pragma unroll
        for (int ni = 0; ni < 4; ni++) {
            long col = bn + nw + ni * 8 + tq * 2;
            float b0 = bias ? bias[col] : 0.f;
            float b1 = bias ? bias[col + 1] : 0.f;
            float v0 = acc[mi][ni][0] + b0, v1 = acc[mi][ni][1] + b1;
            float v2 = acc[mi][ni][2] + b0, v3 = acc[mi][ni][3] + b1;
            if (!act0) { v0 = 0.f; v1 = 0.f; }
            if (!act1) { v2 = 0.f; v3 = 0.f; }
            *(float2*)&C[coff + row0 * ldc + col] = make_float2(v0, v1);
            *(float2*)&C[coff + row1 * ldc + col] = make_float2(v2, v3);
        }
    }
}

// ---------------------------------------------------------------------------
// fp32 tiled SGEMM (kept for tiny latency-bound GEMMs): C = A@W^T + bias
// ---------------------------------------------------------------------------
#define BM 64
#define BN 64
#define BK 16

__global__ __launch_bounds__(256) void sgemm_nt(
    const float* __restrict__ A, const float* __restrict__ W,
    const float* __restrict__ bias, float* __restrict__ C,
    int M, int N, int K, long ldc, long coff)
{
    __shared__ float As[BK][BM];
    __shared__ float Ws[BK][BN];

    const int bm = blockIdx.y * BM;
    const int bn = blockIdx.x * BN;
    const int tid = threadIdx.x;
    const int tr  = tid >> 4;
    const int tc  = tid & 15;
    const int lr  = tid >> 2;
    const int lk  = (tid & 3) * 4;

    float acc[4][4];
#pragma unroll
    for (int i = 0; i < 4; i++)
#pragma unroll
        for (int j = 0; j < 4; j++) acc[i][j] = 0.f;

    for (int k0 = 0; k0 < K; k0 += BK) {
        float4 av = *(const float4*)(&A[(long)(bm + lr) * K + k0 + lk]);
        As[lk + 0][lr] = av.x; As[lk + 1][lr] = av.y;
        As[lk + 2][lr] = av.z; As[lk + 3][lr] = av.w;
        float4 wv = *(const float4*)(&W[(long)(bn + lr) * K + k0 + lk]);
        Ws[lk + 0][lr] = wv.x; Ws[lk + 1][lr] = wv.y;
        Ws[lk + 2][lr] = wv.z; Ws[lk + 3][lr] = wv.w;
        __syncthreads();

#pragma unroll
        for (int kk = 0; kk < BK; kk++) {
            float4 a4 = *(const float4*)(&As[kk][tr * 4]);
            float4 w4 = *(const float4*)(&Ws[kk][tc * 4]);
            float a[4] = {a4.x, a4.y, a4.z, a4.w};
            float w[4] = {w4.x, w4.y, w4.z, w4.w};
#pragma unroll
            for (int i = 0; i < 4; i++)
#pragma unroll
                for (int j = 0; j < 4; j++) acc[i][j] = fmaf(a[i], w[j], acc[i][j]);
        }
        __syncthreads();
    }

#pragma unroll
    for (int i = 0; i < 4; i++) {
        int row = bm + tr * 4 + i;
#pragma unroll
        for (int j = 0; j < 4; j++) {
            int col = bn + tc * 4 + j;
            C[coff + (long)row * ldc + col] = acc[i][j] + (bias ? bias[col] : 0.f);
        }
    }
}

// ---------------------------------------------------------------------------
// Small kernels
// ---------------------------------------------------------------------------
__global__ void k_fmean(const float* __restrict__ features)
{
    int b = blockIdx.x, e = threadIdx.x;
    const float* f = features + (long)b * NP * ND + e;
    float s = 0.f;
#pragma unroll 4
    for (int p = 0; p < NP; p++) s += f[(long)p * ND];
    g_fmean[b * ND + e] = s * (1.0f / (float)NP);
}

// generic fp32 -> (hi, lo) bf16 split
__global__ void k_split(const float* __restrict__ src,
                        __nv_bfloat16* __restrict__ hi,
                        __nv_bfloat16* __restrict__ lo, long n)
{
    long i = (long)blockIdx.x * blockDim.x + threadIdx.x;
    if (i >= n) return;
    split2(src[i], &hi[i], &lo[i]);
}

// pack [w_ih | w_hh] -> hi/lo, and bcat = b_ih + b_hh
__global__ void k_packcat(const float* __restrict__ w_ih, const float* __restrict__ w_hh,
                          const float* __restrict__ b_ih, const float* __restrict__ b_hh)
{
    long idx = (long)blockIdx.x * blockDim.x + threadIdx.x;
    const long total = (long)NG * ZK;
    if (idx < total) {
        int j = (int)(idx / ZK);
        int k = (int)(idx % ZK);
        float v = (k < 1024) ? w_ih[(long)j * 1024 + k]
                             : w_hh[(long)j * 512 + (k - 1024)];
        split2(v, &g_wcath[idx], &g_wcatl[idx]);
    }
    if (idx < NG) g_bcat[idx] = b_ih[idx] + b_hh[idx];
}

// pack [w_dec_att | w_beta] (1024 x 512 fp32) and bias
__global__ void k_packag(const float* __restrict__ w_dec, const float* __restrict__ b_dec,
                         const float* __restrict__ w_beta, const float* __restrict__ b_beta)
{
    long idx = (long)blockIdx.x * blockDim.x + threadIdx.x;
    if (idx < (long)NAG * ND) {
        long half = (long)512 * ND;
        g_wag[idx] = (idx < half) ? w_dec[idx] : w_beta[idx - half];
    }
    if (idx < NAG) g_bag[idx] = (idx < 512) ? b_dec[idx] : b_beta[idx - 512];
}

// e[b,p] = sum_a relu(att1[b,p,a] + att2[b,a]) * w_full[a]
__global__ void k_escore(const float* __restrict__ w_full)
{
    int warp = (int)((blockIdx.x * blockDim.x + threadIdx.x) >> 5);
    int lane = threadIdx.x & 31;
    if (warp >= NB * NP) return;
    int b = warp / NP;
    const float* a1 = g_att1 + (long)warp * ND;
    const float* a2 = g_att2gate + b * NAG;  // att2 in first 512 cols
    float s = 0.f;
    for (int k = lane; k < ND; k += 32) {
        float v = a1[k] + a2[k];
        s = fmaf(fmaxf(v, 0.f), w_full[k], s);
    }
#pragma unroll
    for (int o = 16; o > 0; o >>= 1) s += __shfl_xor_sync(0xffffffffu, s, o);
    if (lane == 0) g_e[warp] = s;
}

__global__ void k_softmax(const int* __restrict__ lengths, float* __restrict__ out,
                          long alpha_off, int t)
{
    int b = blockIdx.x;
    int p = threadIdx.x;  // 256 threads
    __shared__ float red[256];
    float orig = (p < NP) ? g_e[b * NP + p] : -1e30f;
    red[p] = orig; __syncthreads();
#pragma unroll
    for (int s = 128; s > 0; s >>= 1) { if (p < s) red[p] = fmaxf(red[p], red[p + s]); __syncthreads(); }
    float mx = red[0];
    __syncthreads();
    float ex = (p < NP) ? expf(orig - mx) : 0.f;
    red[p] = ex; __syncthreads();
#pragma unroll
    for (int s = 128; s > 0; s >>= 1) { if (p < s) red[p] += red[p + s]; __syncthreads(); }
    float inv = 1.0f / red[0];
    if (p < NP) {
        float a = ex * inv;
        g_alpha[b * NP + p] = a;
        int act = (t < lengths[b] - 1) ? 1 : 0;
        out[alpha_off + ((long)b * NT + t) * NP + p] = act ? a : 0.f;
    }
}

// Build z = [emb | gate*awe | h] directly as hi/lo bf16
__global__ void k_ctx(const float* __restrict__ features,
                      const float* __restrict__ embed_w,
                      const int* __restrict__ captions, int t)
{
    int b = blockIdx.x, e = threadIdx.x;              // 512 threads
    __shared__ float al[NP];
    for (int p = threadIdx.x; p < NP; p += blockDim.x) al[p] = g_alpha[b * NP + p];
    __syncthreads();
    const float* f = features + (long)b * NP * ND + e;
    float s = 0.f;
#pragma unroll 4
    for (int p = 0; p < NP; p++) s = fmaf(al[p], f[(long)p * ND], s);
    float gate = sigf(g_att2gate[b * NAG + 512 + e]);
    float awe = s * gate;
    int tok = captions[b * NL + t];
    float emb = embed_w[(long)tok * ND + e];
    float hv  = g_h[b * ND + e];
    long base = (long)b * ZK;
    split2(emb, &g_zhi[base + e],        &g_zlo[base + e]);
    split2(awe, &g_zhi[base + 512 + e],  &g_zlo[base + 512 + e]);
    split2(hv,  &g_zhi[base + 1024 + e], &g_zlo[base + 1024 + e]);
}

__global__ void k_lstm(const int* __restrict__ lengths, int t)
{
    int b = blockIdx.x, j = threadIdx.x;              // 512 threads
    const float* g = g_gates + b * NG;
    float ig = sigf(g[j]);
    float fg = sigf(g[512 + j]);
    float gg = tanhf(g[1024 + j]);
    float og = sigf(g[1536 + j]);
    float cold = g_c[b * ND + j], hold = g_h[b * ND + j];
    float cn = fg * cold + ig * gg;
    float hn = og * tanhf(cn);
    split2(hn, &g_hnhi[b * ND + j], &g_hnlo[b * ND + j]);
    int act = (t < lengths[b] - 1) ? 1 : 0;
    g_h[b * ND + j] = act ? hn : hold;
    g_c[b * ND + j] = act ? cn : cold;
}

// ---------------------------------------------------------------------------
// Launch
// ---------------------------------------------------------------------------
extern "C" void kernel_launch(void* const* d_in, const int* in_sizes, int n_in,
                              void* d_out, int out_size)
{
    const float* features = (const float*)d_in[0];
    const int*   captions = (const int*)  d_in[1];
    const int*   lengths  = (const int*)  d_in[2];
    const float* w_enc_att= (const float*)d_in[3];
    const float* b_enc_att= (const float*)d_in[4];
    const float* w_dec_att= (const float*)d_in[5];
    const float* b_dec_att= (const float*)d_in[6];
    const float* w_full   = (const float*)d_in[7];
    // d_in[8] = b_full : softmax-invariant constant, unused
    const float* embed_w  = (const float*)d_in[9];
    const float* w_ih     = (const float*)d_in[10];
    const float* b_ih     = (const float*)d_in[11];
    const float* w_hh     = (const float*)d_in[12];
    const float* b_hh     = (const float*)d_in[13];
    const float* w_init_h = (const float*)d_in[14];
    const float* b_init_h = (const float*)d_in[15];
    const float* w_init_c = (const float*)d_in[16];
    const float* b_init_c = (const float*)d_in[17];
    const float* w_beta   = (const float*)d_in[18];
    const float* b_beta   = (const float*)d_in[19];
    const float* w_fc     = (const float*)d_in[20];
    const float* b_fc     = (const float*)d_in[21];
    float* out = (float*)d_out;

    float *p_att1, *p_fmean, *p_h, *p_c, *p_att2gate, *p_gates, *p_wag, *p_bag, *p_bcat;
    __nv_bfloat16 *p_fhi, *p_flo, *p_wfch, *p_wfcl, *p_wcath, *p_wcatl,
                  *p_wench, *p_wencl, *p_zhi, *p_zlo, *p_hnhi, *p_hnlo;
    cudaGetSymbolAddress((void**)&p_att1,     g_att1);
    cudaGetSymbolAddress((void**)&p_fmean,    g_fmean);
    cudaGetSymbolAddress((void**)&p_h,        g_h);
    cudaGetSymbolAddress((void**)&p_c,        g_c);
    cudaGetSymbolAddress((void**)&p_att2gate, g_att2gate);
    cudaGetSymbolAddress((void**)&p_gates,    g_gates);
    cudaGetSymbolAddress((void**)&p_wag,      g_wag);
    cudaGetSymbolAddress((void**)&p_bag,      g_bag);
    cudaGetSymbolAddress((void**)&p_bcat,     g_bcat);
    cudaGetSymbolAddress((void**)&p_fhi,      g_fhi);
    cudaGetSymbolAddress((void**)&p_flo,      g_flo);
    cudaGetSymbolAddress((void**)&p_wfch,     g_wfch);
    cudaGetSymbolAddress((void**)&p_wfcl,     g_wfcl);
    cudaGetSymbolAddress((void**)&p_wcath,    g_wcath);
    cudaGetSymbolAddress((void**)&p_wcatl,    g_wcatl);
    cudaGetSymbolAddress((void**)&p_wench,    g_wench);
    cudaGetSymbolAddress((void**)&p_wencl,    g_wencl);
    cudaGetSymbolAddress((void**)&p_zhi,      g_zhi);
    cudaGetSymbolAddress((void**)&p_zlo,      g_zlo);
    cudaGetSymbolAddress((void**)&p_hnhi,     g_hnhi);
    cudaGetSymbolAddress((void**)&p_hnlo,     g_hnlo);

    const long PRED_SIZE = (long)NB * NT * NV;
    const long ALPHA_OFF = PRED_SIZE;

    // ---- One-time setup ----
    k_fmean<<<NB, ND>>>(features);
    {
        dim3 gi(ND / BN, NB / BM);
        sgemm_nt<<<gi, 256>>>(p_fmean, w_init_h, b_init_h, p_h, NB, ND, ND, ND, 0);
        sgemm_nt<<<gi, 256>>>(p_fmean, w_init_c, b_init_c, p_c, NB, ND, ND, ND, 0);
    }
    {   // conversions / packs
        long nf = (long)NB * NP * ND;
        k_split<<<(int)((nf + 255) / 256), 256>>>(features, p_fhi, p_flo, nf);
        long nw = (long)NV * ND;
        k_split<<<(int)((nw + 255) / 256), 256>>>(w_fc, p_wfch, p_wfcl, nw);
        long ne = (long)ND * ND;
        k_split<<<(int)((ne + 255) / 256), 256>>>(w_enc_att, p_wench, p_wencl, ne);
        long nc = (long)NG * ZK;
        k_packcat<<<(int)((nc + 255) / 256), 256>>>(w_ih, w_hh, b_ih, b_hh);
        long na = (long)NAG * ND;
        k_packag<<<(int)((na + 255) / 256), 256>>>(w_dec_att, b_dec_att, w_beta, b_beta);
    }
    {   // att1 = features @ w_enc_att^T + b_enc_att  (25088 x 512, K=512), bf16x3
        dim3 grid(ND / TBN, (NB * NP) / TBM);   // (8, 196)
        gemm_bf16x3<<<grid, 256>>>(p_fhi, p_flo, p_wench, p_wencl,
                                   b_enc_att, p_att1, ND, ND, 0, nullptr, 0);
    }

    // ---- Decode loop ----
    for (int t = 0; t < NT; t++) {
        // [att2 | gatepre] = h @ [w_dec_att|w_beta]^T + bias   (128 x 1024, K=512)
        {
            dim3 gi(NAG / BN, NB / BM);
            sgemm_nt<<<gi, 256>>>(p_h, p_wag, p_bag, p_att2gate, NB, NAG, ND, NAG, 0);
        }
        {
            int warps = NB * NP;
            int blocks = (warps * 32 + 255) / 256;
            k_escore<<<blocks, 256>>>(w_full);
        }
        k_softmax<<<NB, 256>>>(lengths, out, ALPHA_OFF, t);
        k_ctx<<<NB, ND>>>(features, embed_w, captions, t);

        // gates = z @ wcat^T + bcat  (128 x 2048, K=1536), bf16x3
        {
            dim3 grid(NG / TBN, NB / TBM);      // (32, 1)
            gemm_bf16x3<<<grid, 256>>>(p_zhi, p_zlo, p_wcath, p_wcatl,
                                       p_bcat, p_gates, ZK, NG, 0, nullptr, 0);
        }

        k_lstm<<<NB, ND>>>(lengths, t);

        // preds = h_new @ w_fc^T + b_fc (masked) -> out  (128 x 32000, K=512)
        {
            dim3 grid(NV / TBN, NB / TBM);      // (500, 1)
            gemm_bf16x3<<<grid, 256>>>(p_hnhi, p_hnlo, p_wfch, p_wfcl,
                                       b_fc, out, ND, (long)NT * NV, (long)t * NV,
                                       lengths, t);
        }
    }
}